// round 6
// baseline (speedup 1.0000x reference)
#include <cuda_runtime.h>
#include <cuda_fp16.h>

#define NN 100000
#define NE 1600000
#define NF 64
#define NC 32

// ---------------- scratch (static device memory) --------------------------
__device__ __align__(256) __half2 g_x16[NN * (NF / 2)];   // prescaled x (fp16)
__device__ __align__(256) __half2 g_h1[NN * (NF / 2)];    // layer-1 output (fp16)
__device__ __align__(256) __half2 g_t3[NN * (NC / 2)];    // W3-transformed h2 (fp16)
__device__ int   g_deg_out[NN];            // zero-init; re-zeroed inside scan1
__device__ int   g_deg_in[NN];             // re-zeroed inside scan3
__device__ float g_norm_out[NN];
__device__ float g_norm_in[NN];
__device__ int   g_row_ptr[NN + 1];
__device__ int   g_cursor[NN];
__device__ int   g_partials[64];
__device__ __align__(256) int g_edge_src[NE];

// ---------------- degree histograms (int4: 4 edges/thread) ----------------
__global__ void k_hist(const int4* __restrict__ src4, const int4* __restrict__ dst4) {
    int i = blockIdx.x * blockDim.x + threadIdx.x;
    if (i < NE / 4) {
        int4 s = src4[i];
        int4 d = dst4[i];
        atomicAdd(&g_deg_out[s.x], 1); atomicAdd(&g_deg_out[s.y], 1);
        atomicAdd(&g_deg_out[s.z], 1); atomicAdd(&g_deg_out[s.w], 1);
        atomicAdd(&g_deg_in[d.x], 1);  atomicAdd(&g_deg_in[d.y], 1);
        atomicAdd(&g_deg_in[d.z], 1);  atomicAdd(&g_deg_in[d.w], 1);
    }
}

// ---------------- scan pass 1: norms + block sums + fused prescale --------
#define SCAN_T 512
#define SCAN_I 4
#define SCAN_CHUNK (SCAN_T * SCAN_I)                     // 2048
#define SCAN_NB ((NN + SCAN_CHUNK - 1) / SCAN_CHUNK)     // 49

__global__ __launch_bounds__(SCAN_T) void k_scan1(const float4* __restrict__ x4) {
    __shared__ int sm[SCAN_T];
    __shared__ float snorm[SCAN_CHUNK];
    int tid = threadIdx.x;
    int base_node = blockIdx.x * SCAN_CHUNK;
    int base = base_node + tid * SCAN_I;
    int s = 0;
#pragma unroll
    for (int j = 0; j < SCAN_I; j++) {
        int i = base + j;
        if (i < NN) {
            int di = g_deg_in[i];
            s += di;
            g_norm_in[i]  = rsqrtf((float)max(di, 1));
            float no = rsqrtf((float)max(g_deg_out[i], 1));
            g_norm_out[i] = no;
            snorm[tid * SCAN_I + j] = no;
            g_deg_out[i] = 0;                  // restore for next replay
        }
    }
    sm[tid] = s;
    __syncthreads();
    for (int off = SCAN_T / 2; off > 0; off >>= 1) {
        if (tid < off) sm[tid] += sm[tid + off];
        __syncthreads();
    }
    if (tid == 0) g_partials[blockIdx.x] = sm[0];

    // fused prescale: g_x16[row] = fp16(x[row] * norm_out[row]) for block's rows
    for (int i = tid; i < SCAN_CHUNK * (NF / 4); i += SCAN_T) {
        int r = i >> 4;                    // local row
        int node = base_node + r;
        if (node < NN) {
            float4 v = x4[node * (NF / 4) + (i & 15)];
            float sc = snorm[r];
            g_x16[node * 32 + (i & 15) * 2]     = __floats2half2_rn(v.x * sc, v.y * sc);
            g_x16[node * 32 + (i & 15) * 2 + 1] = __floats2half2_rn(v.z * sc, v.w * sc);
        }
    }
}

// ---------------- scan pass 2 (fused): local partial-prefix + row_ptr -----
__global__ __launch_bounds__(SCAN_T) void k_scan3() {
    __shared__ int sm[SCAN_T];
    __shared__ int pp[SCAN_NB];
    int tid = threadIdx.x;
    if (tid == 0) {
        int run = 0;
#pragma unroll
        for (int b = 0; b < SCAN_NB; b++) { pp[b] = run; run += g_partials[b]; }
        if (blockIdx.x == 0) g_row_ptr[NN] = NE;
    }
    int base = blockIdx.x * SCAN_CHUNK + tid * SCAN_I;
    int c[SCAN_I];
    int s = 0;
#pragma unroll
    for (int j = 0; j < SCAN_I; j++) {
        int i = base + j;
        c[j] = (i < NN) ? g_deg_in[i] : 0;
        if (i < NN) g_deg_in[i] = 0;           // restore for next replay
        s += c[j];
    }
    sm[tid] = s;
    __syncthreads();
    for (int off = 1; off < SCAN_T; off <<= 1) {
        int v = (tid >= off) ? sm[tid - off] : 0;
        __syncthreads();
        sm[tid] += v;
        __syncthreads();
    }
    int excl = sm[tid] - s + pp[blockIdx.x];
#pragma unroll
    for (int j = 0; j < SCAN_I; j++) {
        int i = base + j;
        if (i < NN) { g_row_ptr[i] = excl; g_cursor[i] = excl; }
        excl += c[j];
    }
}

__global__ void k_scatter(const int4* __restrict__ src4, const int4* __restrict__ dst4) {
    int i = blockIdx.x * blockDim.x + threadIdx.x;
    if (i < NE / 4) {
        int4 s = src4[i];
        int4 d = dst4[i];
        g_edge_src[atomicAdd(&g_cursor[d.x], 1)] = s.x;
        g_edge_src[atomicAdd(&g_cursor[d.y], 1)] = s.y;
        g_edge_src[atomicAdd(&g_cursor[d.z], 1)] = s.z;
        g_edge_src[atomicAdd(&g_cursor[d.w], 1)] = s.w;
    }
}

// ---------------- vectorized gather-aggregate (4 edges per warp-LDG, -----
// 8 edges in flight). lane layout: edge slot = lane>>3, fc = (lane&7)*8.
__device__ __forceinline__ void agg64_node(const __half* __restrict__ inh,
                                           int beg, int end, int sub, int fc,
                                           float acc[8]) {
#pragma unroll
    for (int q = 0; q < 8; q++) acc[q] = 0.f;
    int e = beg;
    for (; e + 7 < end; e += 8) {
        int i0 = g_edge_src[e + sub];
        int i1 = g_edge_src[e + 4 + sub];
        uint4 a = *(const uint4*)&inh[i0 * NF + fc];
        uint4 b = *(const uint4*)&inh[i1 * NF + fc];
        float2 f;
        f = __half22float2(*(const __half2*)&a.x); acc[0] += f.x; acc[1] += f.y;
        f = __half22float2(*(const __half2*)&a.y); acc[2] += f.x; acc[3] += f.y;
        f = __half22float2(*(const __half2*)&a.z); acc[4] += f.x; acc[5] += f.y;
        f = __half22float2(*(const __half2*)&a.w); acc[6] += f.x; acc[7] += f.y;
        f = __half22float2(*(const __half2*)&b.x); acc[0] += f.x; acc[1] += f.y;
        f = __half22float2(*(const __half2*)&b.y); acc[2] += f.x; acc[3] += f.y;
        f = __half22float2(*(const __half2*)&b.z); acc[4] += f.x; acc[5] += f.y;
        f = __half22float2(*(const __half2*)&b.w); acc[6] += f.x; acc[7] += f.y;
    }
    for (; e < end; e += 4) {
        int eid = e + sub;
        uint4 v = make_uint4(0u, 0u, 0u, 0u);
        if (eid < end) {
            int s = g_edge_src[eid];
            v = *(const uint4*)&inh[s * NF + fc];
        }
        float2 f;
        f = __half22float2(*(const __half2*)&v.x); acc[0] += f.x; acc[1] += f.y;
        f = __half22float2(*(const __half2*)&v.y); acc[2] += f.x; acc[3] += f.y;
        f = __half22float2(*(const __half2*)&v.z); acc[4] += f.x; acc[5] += f.y;
        f = __half22float2(*(const __half2*)&v.w); acc[6] += f.x; acc[7] += f.y;
    }
#pragma unroll
    for (int q = 0; q < 8; q++) {
        acc[q] += __shfl_xor_sync(0xffffffffu, acc[q], 8);
        acc[q] += __shfl_xor_sync(0xffffffffu, acc[q], 16);
    }
}

// ---------------- fused layer 1: agg + norm_in + GEMM + relu + norm_out ---
__global__ __launch_bounds__(256) void k_layer1(const float* __restrict__ W1,
                                                const float* __restrict__ b1) {
    __shared__ __align__(16) float Ws[NF * NF];
    __shared__ float Is[32][NF + 2];
    int tid = threadIdx.x;
    int row0 = blockIdx.x * 32;
    for (int i = tid; i < NF * NF; i += 256) Ws[i] = W1[i];

    const __half* inh = (const __half*)g_x16;
    int wid = tid >> 5, lane = tid & 31;
    int sub = lane >> 3;
    int fc  = (lane & 7) * 8;
#pragma unroll
    for (int j = 0; j < 4; j++) {
        int nl = (wid << 2) + j;
        int node = row0 + nl;
        float acc[8];
        agg64_node(inh, g_row_ptr[node], g_row_ptr[node + 1], sub, fc, acc);
        if (lane < 8) {
            float ni = g_norm_in[node];
#pragma unroll
            for (int q = 0; q < 8; q++) Is[nl][fc + q] = acc[q] * ni;
        }
    }
    __syncthreads();

    int tcol = (tid & 15) * 4;
    int trow = (tid >> 4) * 2;
    float acc[2][4] = {};
#pragma unroll
    for (int k = 0; k < NF; k++) {
        float4 w = *(const float4*)&Ws[k * NF + tcol];
        float a0 = Is[trow][k], a1 = Is[trow + 1][k];
        acc[0][0] += a0 * w.x; acc[0][1] += a0 * w.y;
        acc[0][2] += a0 * w.z; acc[0][3] += a0 * w.w;
        acc[1][0] += a1 * w.x; acc[1][1] += a1 * w.y;
        acc[1][2] += a1 * w.z; acc[1][3] += a1 * w.w;
    }
    float4 bb = *(const float4*)&b1[tcol];
#pragma unroll
    for (int rr = 0; rr < 2; rr++) {
        int g = row0 + trow + rr;
        float so = g_norm_out[g];
        float o0 = fmaxf(acc[rr][0] + bb.x, 0.f) * so;
        float o1 = fmaxf(acc[rr][1] + bb.y, 0.f) * so;
        float o2 = fmaxf(acc[rr][2] + bb.z, 0.f) * so;
        float o3 = fmaxf(acc[rr][3] + bb.w, 0.f) * so;
        g_h1[g * 32 + (tcol >> 1)]     = __floats2half2_rn(o0, o1);
        g_h1[g * 32 + (tcol >> 1) + 1] = __floats2half2_rn(o2, o3);
    }
}

// layer 2 + fused W3 transform: t3 = (relu(aggW2+b2)*norm_out) @ W3 (fp16) --
__global__ __launch_bounds__(256) void k_layer2(const float* __restrict__ W2,
                                                const float* __restrict__ b2,
                                                const float* __restrict__ W3) {
    __shared__ __align__(16) float Ws[NF * NF];
    __shared__ __align__(16) float W3s[NF * NC];
    __shared__ float Is[32][NF + 2];
    int tid = threadIdx.x;
    int row0 = blockIdx.x * 32;
    for (int i = tid; i < NF * NF; i += 256) Ws[i] = W2[i];
    for (int i = tid; i < NF * NC; i += 256) W3s[i] = W3[i];

    const __half* inh = (const __half*)g_h1;
    int wid = tid >> 5, lane = tid & 31;
    int sub = lane >> 3;
    int fc  = (lane & 7) * 8;
#pragma unroll
    for (int j = 0; j < 4; j++) {
        int nl = (wid << 2) + j;
        int node = row0 + nl;
        float acc[8];
        agg64_node(inh, g_row_ptr[node], g_row_ptr[node + 1], sub, fc, acc);
        if (lane < 8) {
            float ni = g_norm_in[node];
#pragma unroll
            for (int q = 0; q < 8; q++) Is[nl][fc + q] = acc[q] * ni;
        }
    }
    __syncthreads();

    int tcol = (tid & 15) * 4;
    int trow = (tid >> 4) * 2;
    float acc[2][4] = {};
#pragma unroll
    for (int k = 0; k < NF; k++) {
        float4 w = *(const float4*)&Ws[k * NF + tcol];
        float a0 = Is[trow][k], a1 = Is[trow + 1][k];
        acc[0][0] += a0 * w.x; acc[0][1] += a0 * w.y;
        acc[0][2] += a0 * w.z; acc[0][3] += a0 * w.w;
        acc[1][0] += a1 * w.x; acc[1][1] += a1 * w.y;
        acc[1][2] += a1 * w.z; acc[1][3] += a1 * w.w;
    }
    float4 bb = *(const float4*)&b2[tcol];
    float h2v[2][4];
#pragma unroll
    for (int rr = 0; rr < 2; rr++) {
        float so = g_norm_out[row0 + trow + rr];
        h2v[rr][0] = fmaxf(acc[rr][0] + bb.x, 0.f) * so;
        h2v[rr][1] = fmaxf(acc[rr][1] + bb.y, 0.f) * so;
        h2v[rr][2] = fmaxf(acc[rr][2] + bb.z, 0.f) * so;
        h2v[rr][3] = fmaxf(acc[rr][3] + bb.w, 0.f) * so;
    }
    __syncthreads();
#pragma unroll
    for (int rr = 0; rr < 2; rr++) {
        Is[trow + rr][tcol]     = h2v[rr][0];
        Is[trow + rr][tcol + 1] = h2v[rr][1];
        Is[trow + rr][tcol + 2] = h2v[rr][2];
        Is[trow + rr][tcol + 3] = h2v[rr][3];
    }
    __syncthreads();

    // phase 3: t3 = h2n @ W3  (32x32 tile, 1x4 per thread)
    int trow2 = tid >> 3;
    int tcol2 = (tid & 7) * 4;
    float a4[4] = {};
#pragma unroll
    for (int k = 0; k < NF; k++) {
        float h = Is[trow2][k];
        float4 w = *(const float4*)&W3s[k * NC + tcol2];
        a4[0] += h * w.x; a4[1] += h * w.y;
        a4[2] += h * w.z; a4[3] += h * w.w;
    }
    int g = row0 + trow2;
    g_t3[g * 16 + (tcol2 >> 1)]     = __floats2half2_rn(a4[0], a4[1]);
    g_t3[g * 16 + (tcol2 >> 1) + 1] = __floats2half2_rn(a4[2], a4[3]);
}

// ---------------- final: out = norm_in * Agg(t3) + b3 ---------------------
// Warp per node; lane loads uint2 (4 halves): 8 lanes per 64B row, 4 edges/LDG,
// 8 edges in flight.
__global__ void k_out(const float* __restrict__ b3, float* __restrict__ out) {
    int gt = blockIdx.x * blockDim.x + threadIdx.x;
    int w = gt >> 5, lane = gt & 31;
    int sub = lane >> 3;
    int fc  = (lane & 7) * 4;
    const __half* t3 = (const __half*)g_t3;
    int beg = g_row_ptr[w], end = g_row_ptr[w + 1];
    float acc[4] = {};
    int e = beg;
    for (; e + 7 < end; e += 8) {
        int i0 = g_edge_src[e + sub];
        int i1 = g_edge_src[e + 4 + sub];
        uint2 a = *(const uint2*)&t3[i0 * NC + fc];
        uint2 b = *(const uint2*)&t3[i1 * NC + fc];
        float2 f;
        f = __half22float2(*(const __half2*)&a.x); acc[0] += f.x; acc[1] += f.y;
        f = __half22float2(*(const __half2*)&a.y); acc[2] += f.x; acc[3] += f.y;
        f = __half22float2(*(const __half2*)&b.x); acc[0] += f.x; acc[1] += f.y;
        f = __half22float2(*(const __half2*)&b.y); acc[2] += f.x; acc[3] += f.y;
    }
    for (; e < end; e += 4) {
        int eid = e + sub;
        uint2 v = make_uint2(0u, 0u);
        if (eid < end) {
            int s = g_edge_src[eid];
            v = *(const uint2*)&t3[s * NC + fc];
        }
        float2 f;
        f = __half22float2(*(const __half2*)&v.x); acc[0] += f.x; acc[1] += f.y;
        f = __half22float2(*(const __half2*)&v.y); acc[2] += f.x; acc[3] += f.y;
    }
#pragma unroll
    for (int q = 0; q < 4; q++) {
        acc[q] += __shfl_xor_sync(0xffffffffu, acc[q], 8);
        acc[q] += __shfl_xor_sync(0xffffffffu, acc[q], 16);
    }
    if (lane < 8) {
        float ni = g_norm_in[w];
        float4 bb = *(const float4*)&b3[fc];
        float4 o;
        o.x = acc[0] * ni + bb.x;
        o.y = acc[1] * ni + bb.y;
        o.z = acc[2] * ni + bb.z;
        o.w = acc[3] * ni + bb.w;
        *(float4*)&out[w * NC + fc] = o;
    }
}

// ---------------- launch -------------------------------------------------
extern "C" void kernel_launch(void* const* d_in, const int* in_sizes, int n_in,
                              void* d_out, int out_size) {
    const float* x   = (const float*)d_in[0];
    const int*   src = (const int*)d_in[1];
    const int*   dst = (const int*)d_in[2];
    const float* W1  = (const float*)d_in[3];
    const float* b1  = (const float*)d_in[4];
    const float* W2  = (const float*)d_in[5];
    const float* b2  = (const float*)d_in[6];
    const float* W3  = (const float*)d_in[7];
    const float* b3  = (const float*)d_in[8];
    float* out = (float*)d_out;

    const int NB_EDGE4 = (NE / 4 + 255) / 256;          // 1563
    const int NB_OUT   = NN * 32 / 256;                 // 12500

    k_hist<<<NB_EDGE4, 256>>>((const int4*)src, (const int4*)dst);
    k_scan1<<<SCAN_NB, SCAN_T>>>((const float4*)x);
    k_scan3<<<SCAN_NB, SCAN_T>>>();
    k_scatter<<<NB_EDGE4, 256>>>((const int4*)src, (const int4*)dst);
    k_layer1<<<NN / 32, 256>>>(W1, b1);
    k_layer2<<<NN / 32, 256>>>(W2, b2, W3);
    k_out<<<NB_OUT, 256>>>(b3, out);
}

// round 7
// speedup vs baseline: 1.0410x; 1.0410x over previous
#include <cuda_runtime.h>
#include <cuda_fp16.h>

#define NN 100000
#define NE 1600000
#define NF 64
#define NC 32

// ---------------- scratch (static device memory) --------------------------
__device__ __align__(256) __half2 g_x16[NN * (NF / 2)];   // prescaled x (fp16)
__device__ __align__(256) __half2 g_h1[NN * (NF / 2)];    // layer-1 output (fp16)
__device__ __align__(256) __half2 g_t3[NN * (NC / 2)];    // W3-transformed h2 (fp16)
__device__ int   g_deg_out[NN];            // zero-init; re-zeroed inside scan1
__device__ int   g_deg_in[NN];             // re-zeroed inside scan3
__device__ float g_norm_out[NN];
__device__ float g_norm_in[NN];
__device__ int   g_row_ptr[NN + 1];
__device__ int   g_cursor[NN];
__device__ int   g_partials[64];
__device__ __align__(256) int g_edge_src[NE];

// ---------------- degree histograms (8 edges/thread: 2x int4) -------------
__global__ void k_hist(const int4* __restrict__ src4, const int4* __restrict__ dst4) {
    int i = blockIdx.x * blockDim.x + threadIdx.x;   // over NE/8
    if (i < NE / 8) {
        int4 s0 = src4[i * 2], s1 = src4[i * 2 + 1];
        int4 d0 = dst4[i * 2], d1 = dst4[i * 2 + 1];
        atomicAdd(&g_deg_out[s0.x], 1); atomicAdd(&g_deg_out[s0.y], 1);
        atomicAdd(&g_deg_out[s0.z], 1); atomicAdd(&g_deg_out[s0.w], 1);
        atomicAdd(&g_deg_out[s1.x], 1); atomicAdd(&g_deg_out[s1.y], 1);
        atomicAdd(&g_deg_out[s1.z], 1); atomicAdd(&g_deg_out[s1.w], 1);
        atomicAdd(&g_deg_in[d0.x], 1);  atomicAdd(&g_deg_in[d0.y], 1);
        atomicAdd(&g_deg_in[d0.z], 1);  atomicAdd(&g_deg_in[d0.w], 1);
        atomicAdd(&g_deg_in[d1.x], 1);  atomicAdd(&g_deg_in[d1.y], 1);
        atomicAdd(&g_deg_in[d1.z], 1);  atomicAdd(&g_deg_in[d1.w], 1);
    }
}

// ---------------- scan pass 1: norms + block sums + deg_out re-zero -------
#define SCAN_T 512
#define SCAN_I 4
#define SCAN_CHUNK (SCAN_T * SCAN_I)                     // 2048
#define SCAN_NB ((NN + SCAN_CHUNK - 1) / SCAN_CHUNK)     // 49

__global__ __launch_bounds__(SCAN_T) void k_scan1() {
    __shared__ int sm[SCAN_T];
    int tid = threadIdx.x;
    int base = blockIdx.x * SCAN_CHUNK + tid * SCAN_I;
    int s = 0;
#pragma unroll
    for (int j = 0; j < SCAN_I; j++) {
        int i = base + j;
        if (i < NN) {
            int di = g_deg_in[i];
            s += di;
            g_norm_in[i]  = rsqrtf((float)max(di, 1));
            g_norm_out[i] = rsqrtf((float)max(g_deg_out[i], 1));
            g_deg_out[i] = 0;                  // restore for next replay
        }
    }
    sm[tid] = s;
    __syncthreads();
    for (int off = SCAN_T / 2; off > 0; off >>= 1) {
        if (tid < off) sm[tid] += sm[tid + off];
        __syncthreads();
    }
    if (tid == 0) g_partials[blockIdx.x] = sm[0];
}

// ---------------- scan pass 2 (fused): partial-prefix + row_ptr + rezero --
__global__ __launch_bounds__(SCAN_T) void k_scan3() {
    __shared__ int sm[SCAN_T];
    __shared__ int pp[SCAN_NB];
    int tid = threadIdx.x;
    if (tid == 0) {
        int run = 0;
#pragma unroll
        for (int b = 0; b < SCAN_NB; b++) { pp[b] = run; run += g_partials[b]; }
        if (blockIdx.x == 0) g_row_ptr[NN] = NE;
    }
    int base = blockIdx.x * SCAN_CHUNK + tid * SCAN_I;
    int c[SCAN_I];
    int s = 0;
#pragma unroll
    for (int j = 0; j < SCAN_I; j++) {
        int i = base + j;
        c[j] = (i < NN) ? g_deg_in[i] : 0;
        if (i < NN) g_deg_in[i] = 0;           // restore for next replay
        s += c[j];
    }
    sm[tid] = s;
    __syncthreads();
    for (int off = 1; off < SCAN_T; off <<= 1) {
        int v = (tid >= off) ? sm[tid - off] : 0;
        __syncthreads();
        sm[tid] += v;
        __syncthreads();
    }
    int excl = sm[tid] - s + pp[blockIdx.x];
#pragma unroll
    for (int j = 0; j < SCAN_I; j++) {
        int i = base + j;
        if (i < NN) { g_row_ptr[i] = excl; g_cursor[i] = excl; }
        excl += c[j];
    }
}

// ---------------- scatter (8 edges/thread: 2x int4) -----------------------
__global__ void k_scatter(const int4* __restrict__ src4, const int4* __restrict__ dst4) {
    int i = blockIdx.x * blockDim.x + threadIdx.x;   // over NE/8
    if (i < NE / 8) {
        int4 s0 = src4[i * 2], s1 = src4[i * 2 + 1];
        int4 d0 = dst4[i * 2], d1 = dst4[i * 2 + 1];
        g_edge_src[atomicAdd(&g_cursor[d0.x], 1)] = s0.x;
        g_edge_src[atomicAdd(&g_cursor[d0.y], 1)] = s0.y;
        g_edge_src[atomicAdd(&g_cursor[d0.z], 1)] = s0.z;
        g_edge_src[atomicAdd(&g_cursor[d0.w], 1)] = s0.w;
        g_edge_src[atomicAdd(&g_cursor[d1.x], 1)] = s1.x;
        g_edge_src[atomicAdd(&g_cursor[d1.y], 1)] = s1.y;
        g_edge_src[atomicAdd(&g_cursor[d1.z], 1)] = s1.z;
        g_edge_src[atomicAdd(&g_cursor[d1.w], 1)] = s1.w;
    }
}

// ---------------- prescale: g_x16 = fp16(x * norm_out[row]) ---------------
__global__ void k_prescale(const float* __restrict__ x) {
    int i = blockIdx.x * blockDim.x + threadIdx.x;   // over NN*16 float4
    if (i < NN * (NF / 4)) {
        int row = i >> 4;
        float4 v = ((const float4*)x)[i];
        float s = g_norm_out[row];
        g_x16[i * 2]     = __floats2half2_rn(v.x * s, v.y * s);
        g_x16[i * 2 + 1] = __floats2half2_rn(v.z * s, v.w * s);
    }
}

// ---------------- vectorized gather-aggregate (4 edges per warp-LDG, -----
// 8 edges in flight). lane layout: edge slot = lane>>3, fc = (lane&7)*8.
__device__ __forceinline__ void agg64_node(const __half* __restrict__ inh,
                                           int beg, int end, int sub, int fc,
                                           float acc[8]) {
#pragma unroll
    for (int q = 0; q < 8; q++) acc[q] = 0.f;
    int e = beg;
    for (; e + 7 < end; e += 8) {
        int i0 = g_edge_src[e + sub];
        int i1 = g_edge_src[e + 4 + sub];
        uint4 a = *(const uint4*)&inh[i0 * NF + fc];
        uint4 b = *(const uint4*)&inh[i1 * NF + fc];
        float2 f;
        f = __half22float2(*(const __half2*)&a.x); acc[0] += f.x; acc[1] += f.y;
        f = __half22float2(*(const __half2*)&a.y); acc[2] += f.x; acc[3] += f.y;
        f = __half22float2(*(const __half2*)&a.z); acc[4] += f.x; acc[5] += f.y;
        f = __half22float2(*(const __half2*)&a.w); acc[6] += f.x; acc[7] += f.y;
        f = __half22float2(*(const __half2*)&b.x); acc[0] += f.x; acc[1] += f.y;
        f = __half22float2(*(const __half2*)&b.y); acc[2] += f.x; acc[3] += f.y;
        f = __half22float2(*(const __half2*)&b.z); acc[4] += f.x; acc[5] += f.y;
        f = __half22float2(*(const __half2*)&b.w); acc[6] += f.x; acc[7] += f.y;
    }
    for (; e < end; e += 4) {
        int eid = e + sub;
        uint4 v = make_uint4(0u, 0u, 0u, 0u);
        if (eid < end) {
            int s = g_edge_src[eid];
            v = *(const uint4*)&inh[s * NF + fc];
        }
        float2 f;
        f = __half22float2(*(const __half2*)&v.x); acc[0] += f.x; acc[1] += f.y;
        f = __half22float2(*(const __half2*)&v.y); acc[2] += f.x; acc[3] += f.y;
        f = __half22float2(*(const __half2*)&v.z); acc[4] += f.x; acc[5] += f.y;
        f = __half22float2(*(const __half2*)&v.w); acc[6] += f.x; acc[7] += f.y;
    }
#pragma unroll
    for (int q = 0; q < 8; q++) {
        acc[q] += __shfl_xor_sync(0xffffffffu, acc[q], 8);
        acc[q] += __shfl_xor_sync(0xffffffffu, acc[q], 16);
    }
}

// ---------------- fused layer 1: agg + norm_in + GEMM + relu + norm_out ---
__global__ __launch_bounds__(256) void k_layer1(const float* __restrict__ W1,
                                                const float* __restrict__ b1) {
    __shared__ __align__(16) float Ws[NF * NF];
    __shared__ float Is[32][NF + 2];
    int tid = threadIdx.x;
    int row0 = blockIdx.x * 32;
    for (int i = tid; i < NF * NF; i += 256) Ws[i] = W1[i];

    const __half* inh = (const __half*)g_x16;
    int wid = tid >> 5, lane = tid & 31;
    int sub = lane >> 3;
    int fc  = (lane & 7) * 8;
#pragma unroll
    for (int j = 0; j < 4; j++) {
        int nl = (wid << 2) + j;
        int node = row0 + nl;
        float acc[8];
        agg64_node(inh, g_row_ptr[node], g_row_ptr[node + 1], sub, fc, acc);
        if (lane < 8) {
            float ni = g_norm_in[node];
#pragma unroll
            for (int q = 0; q < 8; q++) Is[nl][fc + q] = acc[q] * ni;
        }
    }
    __syncthreads();

    int tcol = (tid & 15) * 4;
    int trow = (tid >> 4) * 2;
    float acc[2][4] = {};
#pragma unroll
    for (int k = 0; k < NF; k++) {
        float4 w = *(const float4*)&Ws[k * NF + tcol];
        float a0 = Is[trow][k], a1 = Is[trow + 1][k];
        acc[0][0] += a0 * w.x; acc[0][1] += a0 * w.y;
        acc[0][2] += a0 * w.z; acc[0][3] += a0 * w.w;
        acc[1][0] += a1 * w.x; acc[1][1] += a1 * w.y;
        acc[1][2] += a1 * w.z; acc[1][3] += a1 * w.w;
    }
    float4 bb = *(const float4*)&b1[tcol];
#pragma unroll
    for (int rr = 0; rr < 2; rr++) {
        int g = row0 + trow + rr;
        float so = g_norm_out[g];
        float o0 = fmaxf(acc[rr][0] + bb.x, 0.f) * so;
        float o1 = fmaxf(acc[rr][1] + bb.y, 0.f) * so;
        float o2 = fmaxf(acc[rr][2] + bb.z, 0.f) * so;
        float o3 = fmaxf(acc[rr][3] + bb.w, 0.f) * so;
        g_h1[g * 32 + (tcol >> 1)]     = __floats2half2_rn(o0, o1);
        g_h1[g * 32 + (tcol >> 1) + 1] = __floats2half2_rn(o2, o3);
    }
}

// layer 2 + fused W3 transform: t3 = (relu(aggW2+b2)*norm_out) @ W3 (fp16) --
__global__ __launch_bounds__(256) void k_layer2(const float* __restrict__ W2,
                                                const float* __restrict__ b2,
                                                const float* __restrict__ W3) {
    __shared__ __align__(16) float Ws[NF * NF];
    __shared__ __align__(16) float W3s[NF * NC];
    __shared__ float Is[32][NF + 2];
    int tid = threadIdx.x;
    int row0 = blockIdx.x * 32;
    for (int i = tid; i < NF * NF; i += 256) Ws[i] = W2[i];
    for (int i = tid; i < NF * NC; i += 256) W3s[i] = W3[i];

    const __half* inh = (const __half*)g_h1;
    int wid = tid >> 5, lane = tid & 31;
    int sub = lane >> 3;
    int fc  = (lane & 7) * 8;
#pragma unroll
    for (int j = 0; j < 4; j++) {
        int nl = (wid << 2) + j;
        int node = row0 + nl;
        float acc[8];
        agg64_node(inh, g_row_ptr[node], g_row_ptr[node + 1], sub, fc, acc);
        if (lane < 8) {
            float ni = g_norm_in[node];
#pragma unroll
            for (int q = 0; q < 8; q++) Is[nl][fc + q] = acc[q] * ni;
        }
    }
    __syncthreads();

    int tcol = (tid & 15) * 4;
    int trow = (tid >> 4) * 2;
    float acc[2][4] = {};
#pragma unroll
    for (int k = 0; k < NF; k++) {
        float4 w = *(const float4*)&Ws[k * NF + tcol];
        float a0 = Is[trow][k], a1 = Is[trow + 1][k];
        acc[0][0] += a0 * w.x; acc[0][1] += a0 * w.y;
        acc[0][2] += a0 * w.z; acc[0][3] += a0 * w.w;
        acc[1][0] += a1 * w.x; acc[1][1] += a1 * w.y;
        acc[1][2] += a1 * w.z; acc[1][3] += a1 * w.w;
    }
    float4 bb = *(const float4*)&b2[tcol];
    float h2v[2][4];
#pragma unroll
    for (int rr = 0; rr < 2; rr++) {
        float so = g_norm_out[row0 + trow + rr];
        h2v[rr][0] = fmaxf(acc[rr][0] + bb.x, 0.f) * so;
        h2v[rr][1] = fmaxf(acc[rr][1] + bb.y, 0.f) * so;
        h2v[rr][2] = fmaxf(acc[rr][2] + bb.z, 0.f) * so;
        h2v[rr][3] = fmaxf(acc[rr][3] + bb.w, 0.f) * so;
    }
    __syncthreads();
#pragma unroll
    for (int rr = 0; rr < 2; rr++) {
        Is[trow + rr][tcol]     = h2v[rr][0];
        Is[trow + rr][tcol + 1] = h2v[rr][1];
        Is[trow + rr][tcol + 2] = h2v[rr][2];
        Is[trow + rr][tcol + 3] = h2v[rr][3];
    }
    __syncthreads();

    // phase 3: t3 = h2n @ W3  (32x32 tile, 1x4 per thread)
    int trow2 = tid >> 3;
    int tcol2 = (tid & 7) * 4;
    float a4[4] = {};
#pragma unroll
    for (int k = 0; k < NF; k++) {
        float h = Is[trow2][k];
        float4 w = *(const float4*)&W3s[k * NC + tcol2];
        a4[0] += h * w.x; a4[1] += h * w.y;
        a4[2] += h * w.z; a4[3] += h * w.w;
    }
    int g = row0 + trow2;
    g_t3[g * 16 + (tcol2 >> 1)]     = __floats2half2_rn(a4[0], a4[1]);
    g_t3[g * 16 + (tcol2 >> 1) + 1] = __floats2half2_rn(a4[2], a4[3]);
}

// ---------------- final: out = norm_in * Agg(t3) + b3 ---------------------
__global__ void k_out(const float* __restrict__ b3, float* __restrict__ out) {
    int gt = blockIdx.x * blockDim.x + threadIdx.x;
    int w = gt >> 5, lane = gt & 31;
    int sub = lane >> 3;
    int fc  = (lane & 7) * 4;
    const __half* t3 = (const __half*)g_t3;
    int beg = g_row_ptr[w], end = g_row_ptr[w + 1];
    float acc[4] = {};
    int e = beg;
    for (; e + 7 < end; e += 8) {
        int i0 = g_edge_src[e + sub];
        int i1 = g_edge_src[e + 4 + sub];
        uint2 a = *(const uint2*)&t3[i0 * NC + fc];
        uint2 b = *(const uint2*)&t3[i1 * NC + fc];
        float2 f;
        f = __half22float2(*(const __half2*)&a.x); acc[0] += f.x; acc[1] += f.y;
        f = __half22float2(*(const __half2*)&a.y); acc[2] += f.x; acc[3] += f.y;
        f = __half22float2(*(const __half2*)&b.x); acc[0] += f.x; acc[1] += f.y;
        f = __half22float2(*(const __half2*)&b.y); acc[2] += f.x; acc[3] += f.y;
    }
    for (; e < end; e += 4) {
        int eid = e + sub;
        uint2 v = make_uint2(0u, 0u);
        if (eid < end) {
            int s = g_edge_src[eid];
            v = *(const uint2*)&t3[s * NC + fc];
        }
        float2 f;
        f = __half22float2(*(const __half2*)&v.x); acc[0] += f.x; acc[1] += f.y;
        f = __half22float2(*(const __half2*)&v.y); acc[2] += f.x; acc[3] += f.y;
    }
#pragma unroll
    for (int q = 0; q < 4; q++) {
        acc[q] += __shfl_xor_sync(0xffffffffu, acc[q], 8);
        acc[q] += __shfl_xor_sync(0xffffffffu, acc[q], 16);
    }
    if (lane < 8) {
        float ni = g_norm_in[w];
        float4 bb = *(const float4*)&b3[fc];
        float4 o;
        o.x = acc[0] * ni + bb.x;
        o.y = acc[1] * ni + bb.y;
        o.z = acc[2] * ni + bb.z;
        o.w = acc[3] * ni + bb.w;
        *(float4*)&out[w * NC + fc] = o;
    }
}

// ---------------- launch -------------------------------------------------
extern "C" void kernel_launch(void* const* d_in, const int* in_sizes, int n_in,
                              void* d_out, int out_size) {
    const float* x   = (const float*)d_in[0];
    const int*   src = (const int*)d_in[1];
    const int*   dst = (const int*)d_in[2];
    const float* W1  = (const float*)d_in[3];
    const float* b1  = (const float*)d_in[4];
    const float* W2  = (const float*)d_in[5];
    const float* b2  = (const float*)d_in[6];
    const float* W3  = (const float*)d_in[7];
    const float* b3  = (const float*)d_in[8];
    float* out = (float*)d_out;

    const int NB_EDGE8 = (NE / 8 + 255) / 256;          // 782
    const int NB_PRE   = (NN * (NF / 4) + 255) / 256;   // 6250
    const int NB_OUT   = NN * 32 / 256;                 // 12500

    k_hist<<<NB_EDGE8, 256>>>((const int4*)src, (const int4*)dst);
    k_scan1<<<SCAN_NB, SCAN_T>>>();
    k_scan3<<<SCAN_NB, SCAN_T>>>();
    k_scatter<<<NB_EDGE8, 256>>>((const int4*)src, (const int4*)dst);
    k_prescale<<<NB_PRE, 256>>>(x);
    k_layer1<<<NN / 32, 256>>>(W1, b1);
    k_layer2<<<NN / 32, 256>>>(W2, b2, W3);
    k_out<<<NB_OUT, 256>>>(b3, out);
}

// round 8
// speedup vs baseline: 1.0749x; 1.0326x over previous
#include <cuda_runtime.h>
#include <cuda_fp16.h>

#define NN 100000
#define NE 1600000
#define NF 64
#define NC 32

// ---------------- scratch (static device memory) --------------------------
__device__ __align__(256) __half2 g_x16[NN * (NF / 2)];   // prescaled x (fp16)
__device__ __align__(256) __half2 g_h1[NN * (NF / 2)];    // layer-1 output (fp16)
__device__ __align__(256) __half2 g_t3[NN * (NC / 2)];    // W3-transformed h2 (fp16)
__device__ int   g_deg_out[NN];            // zero-init; re-zeroed inside scan1
__device__ int   g_deg_in[NN];             // re-zeroed inside scan3
__device__ float g_norm_out[NN];
__device__ float g_norm_in[NN];
__device__ int   g_row_ptr[NN + 1];
__device__ int   g_cursor[NN];
__device__ int   g_partials[64];
__device__ __align__(256) int g_edge_src[NE];

// ---------------- degree histograms (split; 4 edges/thread) ---------------
__global__ void k_hist_in(const int4* __restrict__ dst4) {
    int i = blockIdx.x * blockDim.x + threadIdx.x;
    if (i < NE / 4) {
        int4 d = dst4[i];
        atomicAdd(&g_deg_in[d.x], 1); atomicAdd(&g_deg_in[d.y], 1);
        atomicAdd(&g_deg_in[d.z], 1); atomicAdd(&g_deg_in[d.w], 1);
    }
}

__global__ void k_hist_out(const int4* __restrict__ src4) {
    int i = blockIdx.x * blockDim.x + threadIdx.x;
    if (i < NE / 4) {
        int4 s = src4[i];
        atomicAdd(&g_deg_out[s.x], 1); atomicAdd(&g_deg_out[s.y], 1);
        atomicAdd(&g_deg_out[s.z], 1); atomicAdd(&g_deg_out[s.w], 1);
    }
}

// ---------------- scan pass 1: norms + block sums + deg_out re-zero -------
#define SCAN_T 512
#define SCAN_I 4
#define SCAN_CHUNK (SCAN_T * SCAN_I)                     // 2048
#define SCAN_NB ((NN + SCAN_CHUNK - 1) / SCAN_CHUNK)     // 49

__global__ __launch_bounds__(SCAN_T) void k_scan1() {
    __shared__ int sm[SCAN_T];
    int tid = threadIdx.x;
    int base = blockIdx.x * SCAN_CHUNK + tid * SCAN_I;
    int s = 0;
#pragma unroll
    for (int j = 0; j < SCAN_I; j++) {
        int i = base + j;
        if (i < NN) {
            int di = g_deg_in[i];
            s += di;
            g_norm_in[i]  = rsqrtf((float)max(di, 1));
            g_norm_out[i] = rsqrtf((float)max(g_deg_out[i], 1));
            g_deg_out[i] = 0;                  // restore for next replay
        }
    }
    sm[tid] = s;
    __syncthreads();
    for (int off = SCAN_T / 2; off > 0; off >>= 1) {
        if (tid < off) sm[tid] += sm[tid + off];
        __syncthreads();
    }
    if (tid == 0) g_partials[blockIdx.x] = sm[0];
}

// ---------------- scan pass 2 (fused): partial-prefix + row_ptr + rezero --
__global__ __launch_bounds__(SCAN_T) void k_scan3() {
    __shared__ int sm[SCAN_T];
    __shared__ int pp[SCAN_NB];
    int tid = threadIdx.x;
    if (tid == 0) {
        int run = 0;
#pragma unroll
        for (int b = 0; b < SCAN_NB; b++) { pp[b] = run; run += g_partials[b]; }
        if (blockIdx.x == 0) g_row_ptr[NN] = NE;
    }
    int base = blockIdx.x * SCAN_CHUNK + tid * SCAN_I;
    int c[SCAN_I];
    int s = 0;
#pragma unroll
    for (int j = 0; j < SCAN_I; j++) {
        int i = base + j;
        c[j] = (i < NN) ? g_deg_in[i] : 0;
        if (i < NN) g_deg_in[i] = 0;           // restore for next replay
        s += c[j];
    }
    sm[tid] = s;
    __syncthreads();
    for (int off = 1; off < SCAN_T; off <<= 1) {
        int v = (tid >= off) ? sm[tid - off] : 0;
        __syncthreads();
        sm[tid] += v;
        __syncthreads();
    }
    int excl = sm[tid] - s + pp[blockIdx.x];
#pragma unroll
    for (int j = 0; j < SCAN_I; j++) {
        int i = base + j;
        if (i < NN) { g_row_ptr[i] = excl; g_cursor[i] = excl; }
        excl += c[j];
    }
}

// ---------------- scatter (4 edges/thread) --------------------------------
__global__ void k_scatter(const int4* __restrict__ src4, const int4* __restrict__ dst4) {
    int i = blockIdx.x * blockDim.x + threadIdx.x;
    if (i < NE / 4) {
        int4 s = src4[i];
        int4 d = dst4[i];
        g_edge_src[atomicAdd(&g_cursor[d.x], 1)] = s.x;
        g_edge_src[atomicAdd(&g_cursor[d.y], 1)] = s.y;
        g_edge_src[atomicAdd(&g_cursor[d.z], 1)] = s.z;
        g_edge_src[atomicAdd(&g_cursor[d.w], 1)] = s.w;
    }
}

// ---------------- prescale: g_x16 = fp16(x * norm_out[row]) ---------------
__global__ void k_prescale(const float* __restrict__ x) {
    int i = blockIdx.x * blockDim.x + threadIdx.x;   // over NN*16 float4
    if (i < NN * (NF / 4)) {
        int row = i >> 4;
        float4 v = ((const float4*)x)[i];
        float s = g_norm_out[row];
        g_x16[i * 2]     = __floats2half2_rn(v.x * s, v.y * s);
        g_x16[i * 2 + 1] = __floats2half2_rn(v.z * s, v.w * s);
    }
}

// ---------------- vectorized gather-aggregate (4 edges per warp-LDG, -----
// 8 edges in flight). lane layout: edge slot = lane>>3, fc = (lane&7)*8.
__device__ __forceinline__ void agg64_node(const __half* __restrict__ inh,
                                           int beg, int end, int sub, int fc,
                                           float acc[8]) {
#pragma unroll
    for (int q = 0; q < 8; q++) acc[q] = 0.f;
    int e = beg;
    for (; e + 7 < end; e += 8) {
        int i0 = g_edge_src[e + sub];
        int i1 = g_edge_src[e + 4 + sub];
        uint4 a = *(const uint4*)&inh[i0 * NF + fc];
        uint4 b = *(const uint4*)&inh[i1 * NF + fc];
        float2 f;
        f = __half22float2(*(const __half2*)&a.x); acc[0] += f.x; acc[1] += f.y;
        f = __half22float2(*(const __half2*)&a.y); acc[2] += f.x; acc[3] += f.y;
        f = __half22float2(*(const __half2*)&a.z); acc[4] += f.x; acc[5] += f.y;
        f = __half22float2(*(const __half2*)&a.w); acc[6] += f.x; acc[7] += f.y;
        f = __half22float2(*(const __half2*)&b.x); acc[0] += f.x; acc[1] += f.y;
        f = __half22float2(*(const __half2*)&b.y); acc[2] += f.x; acc[3] += f.y;
        f = __half22float2(*(const __half2*)&b.z); acc[4] += f.x; acc[5] += f.y;
        f = __half22float2(*(const __half2*)&b.w); acc[6] += f.x; acc[7] += f.y;
    }
    for (; e < end; e += 4) {
        int eid = e + sub;
        uint4 v = make_uint4(0u, 0u, 0u, 0u);
        if (eid < end) {
            int s = g_edge_src[eid];
            v = *(const uint4*)&inh[s * NF + fc];
        }
        float2 f;
        f = __half22float2(*(const __half2*)&v.x); acc[0] += f.x; acc[1] += f.y;
        f = __half22float2(*(const __half2*)&v.y); acc[2] += f.x; acc[3] += f.y;
        f = __half22float2(*(const __half2*)&v.z); acc[4] += f.x; acc[5] += f.y;
        f = __half22float2(*(const __half2*)&v.w); acc[6] += f.x; acc[7] += f.y;
    }
#pragma unroll
    for (int q = 0; q < 8; q++) {
        acc[q] += __shfl_xor_sync(0xffffffffu, acc[q], 8);
        acc[q] += __shfl_xor_sync(0xffffffffu, acc[q], 16);
    }
}

// ---------------- fused layer 1: agg + norm_in + GEMM + relu + norm_out ---
__global__ __launch_bounds__(256) void k_layer1(const float* __restrict__ W1,
                                                const float* __restrict__ b1) {
    __shared__ __align__(16) float Ws[NF * NF];
    __shared__ float Is[32][NF + 2];
    int tid = threadIdx.x;
    int row0 = blockIdx.x * 32;
    for (int i = tid; i < NF * NF; i += 256) Ws[i] = W1[i];

    const __half* inh = (const __half*)g_x16;
    int wid = tid >> 5, lane = tid & 31;
    int sub = lane >> 3;
    int fc  = (lane & 7) * 8;
#pragma unroll
    for (int j = 0; j < 4; j++) {
        int nl = (wid << 2) + j;
        int node = row0 + nl;
        float acc[8];
        agg64_node(inh, g_row_ptr[node], g_row_ptr[node + 1], sub, fc, acc);
        if (lane < 8) {
            float ni = g_norm_in[node];
#pragma unroll
            for (int q = 0; q < 8; q++) Is[nl][fc + q] = acc[q] * ni;
        }
    }
    __syncthreads();

    int tcol = (tid & 15) * 4;
    int trow = (tid >> 4) * 2;
    float acc[2][4] = {};
#pragma unroll
    for (int k = 0; k < NF; k++) {
        float4 w = *(const float4*)&Ws[k * NF + tcol];
        float a0 = Is[trow][k], a1 = Is[trow + 1][k];
        acc[0][0] += a0 * w.x; acc[0][1] += a0 * w.y;
        acc[0][2] += a0 * w.z; acc[0][3] += a0 * w.w;
        acc[1][0] += a1 * w.x; acc[1][1] += a1 * w.y;
        acc[1][2] += a1 * w.z; acc[1][3] += a1 * w.w;
    }
    float4 bb = *(const float4*)&b1[tcol];
#pragma unroll
    for (int rr = 0; rr < 2; rr++) {
        int g = row0 + trow + rr;
        float so = g_norm_out[g];
        float o0 = fmaxf(acc[rr][0] + bb.x, 0.f) * so;
        float o1 = fmaxf(acc[rr][1] + bb.y, 0.f) * so;
        float o2 = fmaxf(acc[rr][2] + bb.z, 0.f) * so;
        float o3 = fmaxf(acc[rr][3] + bb.w, 0.f) * so;
        g_h1[g * 32 + (tcol >> 1)]     = __floats2half2_rn(o0, o1);
        g_h1[g * 32 + (tcol >> 1) + 1] = __floats2half2_rn(o2, o3);
    }
}

// layer 2 + fused W3 transform: t3 = (relu(aggW2+b2)*norm_out) @ W3 (fp16) --
__global__ __launch_bounds__(256) void k_layer2(const float* __restrict__ W2,
                                                const float* __restrict__ b2,
                                                const float* __restrict__ W3) {
    __shared__ __align__(16) float Ws[NF * NF];
    __shared__ __align__(16) float W3s[NF * NC];
    __shared__ float Is[32][NF + 2];
    int tid = threadIdx.x;
    int row0 = blockIdx.x * 32;
    for (int i = tid; i < NF * NF; i += 256) Ws[i] = W2[i];
    for (int i = tid; i < NF * NC; i += 256) W3s[i] = W3[i];

    const __half* inh = (const __half*)g_h1;
    int wid = tid >> 5, lane = tid & 31;
    int sub = lane >> 3;
    int fc  = (lane & 7) * 8;
#pragma unroll
    for (int j = 0; j < 4; j++) {
        int nl = (wid << 2) + j;
        int node = row0 + nl;
        float acc[8];
        agg64_node(inh, g_row_ptr[node], g_row_ptr[node + 1], sub, fc, acc);
        if (lane < 8) {
            float ni = g_norm_in[node];
#pragma unroll
            for (int q = 0; q < 8; q++) Is[nl][fc + q] = acc[q] * ni;
        }
    }
    __syncthreads();

    int tcol = (tid & 15) * 4;
    int trow = (tid >> 4) * 2;
    float acc[2][4] = {};
#pragma unroll
    for (int k = 0; k < NF; k++) {
        float4 w = *(const float4*)&Ws[k * NF + tcol];
        float a0 = Is[trow][k], a1 = Is[trow + 1][k];
        acc[0][0] += a0 * w.x; acc[0][1] += a0 * w.y;
        acc[0][2] += a0 * w.z; acc[0][3] += a0 * w.w;
        acc[1][0] += a1 * w.x; acc[1][1] += a1 * w.y;
        acc[1][2] += a1 * w.z; acc[1][3] += a1 * w.w;
    }
    float4 bb = *(const float4*)&b2[tcol];
    float h2v[2][4];
#pragma unroll
    for (int rr = 0; rr < 2; rr++) {
        float so = g_norm_out[row0 + trow + rr];
        h2v[rr][0] = fmaxf(acc[rr][0] + bb.x, 0.f) * so;
        h2v[rr][1] = fmaxf(acc[rr][1] + bb.y, 0.f) * so;
        h2v[rr][2] = fmaxf(acc[rr][2] + bb.z, 0.f) * so;
        h2v[rr][3] = fmaxf(acc[rr][3] + bb.w, 0.f) * so;
    }
    __syncthreads();
#pragma unroll
    for (int rr = 0; rr < 2; rr++) {
        Is[trow + rr][tcol]     = h2v[rr][0];
        Is[trow + rr][tcol + 1] = h2v[rr][1];
        Is[trow + rr][tcol + 2] = h2v[rr][2];
        Is[trow + rr][tcol + 3] = h2v[rr][3];
    }
    __syncthreads();

    // phase 3: t3 = h2n @ W3  (32x32 tile, 1x4 per thread)
    int trow2 = tid >> 3;
    int tcol2 = (tid & 7) * 4;
    float a4[4] = {};
#pragma unroll
    for (int k = 0; k < NF; k++) {
        float h = Is[trow2][k];
        float4 w = *(const float4*)&W3s[k * NC + tcol2];
        a4[0] += h * w.x; a4[1] += h * w.y;
        a4[2] += h * w.z; a4[3] += h * w.w;
    }
    int g = row0 + trow2;
    g_t3[g * 16 + (tcol2 >> 1)]     = __floats2half2_rn(a4[0], a4[1]);
    g_t3[g * 16 + (tcol2 >> 1) + 1] = __floats2half2_rn(a4[2], a4[3]);
}

// ---------------- final: out = norm_in * Agg(t3) + b3 ---------------------
__global__ void k_out(const float* __restrict__ b3, float* __restrict__ out) {
    int gt = blockIdx.x * blockDim.x + threadIdx.x;
    int w = gt >> 5, lane = gt & 31;
    int sub = lane >> 3;
    int fc  = (lane & 7) * 4;
    const __half* t3 = (const __half*)g_t3;
    int beg = g_row_ptr[w], end = g_row_ptr[w + 1];
    float acc[4] = {};
    int e = beg;
    for (; e + 7 < end; e += 8) {
        int i0 = g_edge_src[e + sub];
        int i1 = g_edge_src[e + 4 + sub];
        uint2 a = *(const uint2*)&t3[i0 * NC + fc];
        uint2 b = *(const uint2*)&t3[i1 * NC + fc];
        float2 f;
        f = __half22float2(*(const __half2*)&a.x); acc[0] += f.x; acc[1] += f.y;
        f = __half22float2(*(const __half2*)&a.y); acc[2] += f.x; acc[3] += f.y;
        f = __half22float2(*(const __half2*)&b.x); acc[0] += f.x; acc[1] += f.y;
        f = __half22float2(*(const __half2*)&b.y); acc[2] += f.x; acc[3] += f.y;
    }
    for (; e < end; e += 4) {
        int eid = e + sub;
        uint2 v = make_uint2(0u, 0u);
        if (eid < end) {
            int s = g_edge_src[eid];
            v = *(const uint2*)&t3[s * NC + fc];
        }
        float2 f;
        f = __half22float2(*(const __half2*)&v.x); acc[0] += f.x; acc[1] += f.y;
        f = __half22float2(*(const __half2*)&v.y); acc[2] += f.x; acc[3] += f.y;
    }
#pragma unroll
    for (int q = 0; q < 4; q++) {
        acc[q] += __shfl_xor_sync(0xffffffffu, acc[q], 8);
        acc[q] += __shfl_xor_sync(0xffffffffu, acc[q], 16);
    }
    if (lane < 8) {
        float ni = g_norm_in[w];
        float4 bb = *(const float4*)&b3[fc];
        float4 o;
        o.x = acc[0] * ni + bb.x;
        o.y = acc[1] * ni + bb.y;
        o.z = acc[2] * ni + bb.z;
        o.w = acc[3] * ni + bb.w;
        *(float4*)&out[w * NC + fc] = o;
    }
}

// ---------------- launch -------------------------------------------------
// Fork/join on a second (non-blocking) stream; streams & events are created
// once (resource setup only — the captured work is identical every call).
extern "C" void kernel_launch(void* const* d_in, const int* in_sizes, int n_in,
                              void* d_out, int out_size) {
    const float* x   = (const float*)d_in[0];
    const int*   src = (const int*)d_in[1];
    const int*   dst = (const int*)d_in[2];
    const float* W1  = (const float*)d_in[3];
    const float* b1  = (const float*)d_in[4];
    const float* W2  = (const float*)d_in[5];
    const float* b2  = (const float*)d_in[6];
    const float* W3  = (const float*)d_in[7];
    const float* b3  = (const float*)d_in[8];
    float* out = (float*)d_out;

    static cudaStream_t s2 = nullptr;
    static cudaEvent_t evA = nullptr, evB = nullptr, evC = nullptr, evD = nullptr;
    if (s2 == nullptr) {
        cudaStreamCreateWithFlags(&s2, cudaStreamNonBlocking);
        cudaEventCreateWithFlags(&evA, cudaEventDisableTiming);
        cudaEventCreateWithFlags(&evB, cudaEventDisableTiming);
        cudaEventCreateWithFlags(&evC, cudaEventDisableTiming);
        cudaEventCreateWithFlags(&evD, cudaEventDisableTiming);
    }

    const int NB_EDGE4 = (NE / 4 + 255) / 256;          // 1563
    const int NB_PRE   = (NN * (NF / 4) + 255) / 256;   // 6250
    const int NB_OUT   = NN * 32 / 256;                 // 12500

    // fork: hist_out on s2 concurrent with hist_in on main stream
    cudaEventRecord(evA, 0);
    cudaStreamWaitEvent(s2, evA, 0);
    k_hist_out<<<NB_EDGE4, 256, 0, s2>>>((const int4*)src);
    k_hist_in<<<NB_EDGE4, 256>>>((const int4*)dst);
    cudaEventRecord(evB, s2);
    cudaStreamWaitEvent(0, evB, 0);

    k_scan1<<<SCAN_NB, SCAN_T>>>();

    // fork: prescale (needs only norm_out) concurrent with scan3 + scatter
    cudaEventRecord(evC, 0);
    cudaStreamWaitEvent(s2, evC, 0);
    k_prescale<<<NB_PRE, 256, 0, s2>>>(x);
    k_scan3<<<SCAN_NB, SCAN_T>>>();
    k_scatter<<<NB_EDGE4, 256>>>((const int4*)src, (const int4*)dst);
    cudaEventRecord(evD, s2);
    cudaStreamWaitEvent(0, evD, 0);

    k_layer1<<<NN / 32, 256>>>(W1, b1);
    k_layer2<<<NN / 32, 256>>>(W2, b2, W3);
    k_out<<<NB_OUT, 256>>>(b3, out);
}

// round 9
// speedup vs baseline: 1.1060x; 1.0290x over previous
#include <cuda_runtime.h>
#include <cuda_fp16.h>
#include <mma.h>

using namespace nvcuda;

#define NN 100000
#define NE 1600000
#define NF 64
#define NC 32
#define OS_LD 68   // float smem epilogue row stride

// ---------------- scratch (static device memory) --------------------------
__device__ __align__(256) __half2 g_x16[NN * (NF / 2)];   // prescaled x (fp16)
__device__ __align__(256) __half2 g_h1[NN * (NF / 2)];    // layer-1 output (fp16)
__device__ __align__(256) __half2 g_t3[NN * (NC / 2)];    // W3-transformed h2 (fp16)
__device__ int   g_deg_out[NN];            // zero-init; re-zeroed inside scan1
__device__ int   g_deg_in[NN];             // re-zeroed inside scan3
__device__ float g_norm_out[NN];
__device__ float g_norm_in[NN];
__device__ int   g_row_ptr[NN + 1];
__device__ int   g_cursor[NN];
__device__ int   g_partials[64];
__device__ __align__(256) int g_edge_src[NE];

// ---------------- degree histograms (split; 4 edges/thread) ---------------
__global__ void k_hist_in(const int4* __restrict__ dst4) {
    int i = blockIdx.x * blockDim.x + threadIdx.x;
    if (i < NE / 4) {
        int4 d = dst4[i];
        atomicAdd(&g_deg_in[d.x], 1); atomicAdd(&g_deg_in[d.y], 1);
        atomicAdd(&g_deg_in[d.z], 1); atomicAdd(&g_deg_in[d.w], 1);
    }
}

__global__ void k_hist_out(const int4* __restrict__ src4) {
    int i = blockIdx.x * blockDim.x + threadIdx.x;
    if (i < NE / 4) {
        int4 s = src4[i];
        atomicAdd(&g_deg_out[s.x], 1); atomicAdd(&g_deg_out[s.y], 1);
        atomicAdd(&g_deg_out[s.z], 1); atomicAdd(&g_deg_out[s.w], 1);
    }
}

// ---------------- scan pass 1: norms + block sums + deg_out re-zero -------
#define SCAN_T 512
#define SCAN_I 4
#define SCAN_CHUNK (SCAN_T * SCAN_I)                     // 2048
#define SCAN_NB ((NN + SCAN_CHUNK - 1) / SCAN_CHUNK)     // 49

__global__ __launch_bounds__(SCAN_T) void k_scan1() {
    __shared__ int sm[SCAN_T];
    int tid = threadIdx.x;
    int base = blockIdx.x * SCAN_CHUNK + tid * SCAN_I;
    int s = 0;
#pragma unroll
    for (int j = 0; j < SCAN_I; j++) {
        int i = base + j;
        if (i < NN) {
            int di = g_deg_in[i];
            s += di;
            g_norm_in[i]  = rsqrtf((float)max(di, 1));
            g_norm_out[i] = rsqrtf((float)max(g_deg_out[i], 1));
            g_deg_out[i] = 0;                  // restore for next replay
        }
    }
    sm[tid] = s;
    __syncthreads();
    for (int off = SCAN_T / 2; off > 0; off >>= 1) {
        if (tid < off) sm[tid] += sm[tid + off];
        __syncthreads();
    }
    if (tid == 0) g_partials[blockIdx.x] = sm[0];
}

// ---------------- scan pass 2 (fused): partial-prefix + row_ptr + rezero --
__global__ __launch_bounds__(SCAN_T) void k_scan3() {
    __shared__ int sm[SCAN_T];
    __shared__ int pp[SCAN_NB];
    int tid = threadIdx.x;
    if (tid == 0) {
        int run = 0;
#pragma unroll
        for (int b = 0; b < SCAN_NB; b++) { pp[b] = run; run += g_partials[b]; }
        if (blockIdx.x == 0) g_row_ptr[NN] = NE;
    }
    int base = blockIdx.x * SCAN_CHUNK + tid * SCAN_I;
    int c[SCAN_I];
    int s = 0;
#pragma unroll
    for (int j = 0; j < SCAN_I; j++) {
        int i = base + j;
        c[j] = (i < NN) ? g_deg_in[i] : 0;
        if (i < NN) g_deg_in[i] = 0;           // restore for next replay
        s += c[j];
    }
    sm[tid] = s;
    __syncthreads();
    for (int off = 1; off < SCAN_T; off <<= 1) {
        int v = (tid >= off) ? sm[tid - off] : 0;
        __syncthreads();
        sm[tid] += v;
        __syncthreads();
    }
    int excl = sm[tid] - s + pp[blockIdx.x];
#pragma unroll
    for (int j = 0; j < SCAN_I; j++) {
        int i = base + j;
        if (i < NN) { g_row_ptr[i] = excl; g_cursor[i] = excl; }
        excl += c[j];
    }
}

// ---------------- scatter (4 edges/thread) --------------------------------
__global__ void k_scatter(const int4* __restrict__ src4, const int4* __restrict__ dst4) {
    int i = blockIdx.x * blockDim.x + threadIdx.x;
    if (i < NE / 4) {
        int4 s = src4[i];
        int4 d = dst4[i];
        g_edge_src[atomicAdd(&g_cursor[d.x], 1)] = s.x;
        g_edge_src[atomicAdd(&g_cursor[d.y], 1)] = s.y;
        g_edge_src[atomicAdd(&g_cursor[d.z], 1)] = s.z;
        g_edge_src[atomicAdd(&g_cursor[d.w], 1)] = s.w;
    }
}

// ---------------- prescale: g_x16 = fp16(x * norm_out[row]) ---------------
__global__ void k_prescale(const float* __restrict__ x) {
    int i = blockIdx.x * blockDim.x + threadIdx.x;   // over NN*16 float4
    if (i < NN * (NF / 4)) {
        int row = i >> 4;
        float4 v = ((const float4*)x)[i];
        float s = g_norm_out[row];
        g_x16[i * 2]     = __floats2half2_rn(v.x * s, v.y * s);
        g_x16[i * 2 + 1] = __floats2half2_rn(v.z * s, v.w * s);
    }
}

// ---------------- vectorized gather-aggregate (4 edges per warp-LDG, -----
// 8 edges in flight). lane layout: edge slot = lane>>3, fc = (lane&7)*8.
__device__ __forceinline__ void agg64_node(const __half* __restrict__ inh,
                                           int beg, int end, int sub, int fc,
                                           float acc[8]) {
#pragma unroll
    for (int q = 0; q < 8; q++) acc[q] = 0.f;
    int e = beg;
    for (; e + 7 < end; e += 8) {
        int i0 = g_edge_src[e + sub];
        int i1 = g_edge_src[e + 4 + sub];
        uint4 a = *(const uint4*)&inh[i0 * NF + fc];
        uint4 b = *(const uint4*)&inh[i1 * NF + fc];
        float2 f;
        f = __half22float2(*(const __half2*)&a.x); acc[0] += f.x; acc[1] += f.y;
        f = __half22float2(*(const __half2*)&a.y); acc[2] += f.x; acc[3] += f.y;
        f = __half22float2(*(const __half2*)&a.z); acc[4] += f.x; acc[5] += f.y;
        f = __half22float2(*(const __half2*)&a.w); acc[6] += f.x; acc[7] += f.y;
        f = __half22float2(*(const __half2*)&b.x); acc[0] += f.x; acc[1] += f.y;
        f = __half22float2(*(const __half2*)&b.y); acc[2] += f.x; acc[3] += f.y;
        f = __half22float2(*(const __half2*)&b.z); acc[4] += f.x; acc[5] += f.y;
        f = __half22float2(*(const __half2*)&b.w); acc[6] += f.x; acc[7] += f.y;
    }
    for (; e < end; e += 4) {
        int eid = e + sub;
        uint4 v = make_uint4(0u, 0u, 0u, 0u);
        if (eid < end) {
            int s = g_edge_src[eid];
            v = *(const uint4*)&inh[s * NF + fc];
        }
        float2 f;
        f = __half22float2(*(const __half2*)&v.x); acc[0] += f.x; acc[1] += f.y;
        f = __half22float2(*(const __half2*)&v.y); acc[2] += f.x; acc[3] += f.y;
        f = __half22float2(*(const __half2*)&v.z); acc[4] += f.x; acc[5] += f.y;
        f = __half22float2(*(const __half2*)&v.w); acc[6] += f.x; acc[7] += f.y;
    }
#pragma unroll
    for (int q = 0; q < 8; q++) {
        acc[q] += __shfl_xor_sync(0xffffffffu, acc[q], 8);
        acc[q] += __shfl_xor_sync(0xffffffffu, acc[q], 16);
    }
}

// ---------------- fused layer 1: agg + norm_in + wmma GEMM + epilogue -----
__global__ __launch_bounds__(256) void k_layer1(const float* __restrict__ W1,
                                                const float* __restrict__ b1) {
    __shared__ __align__(16) __half Wh[NF * NF];       // W1 fp16
    __shared__ __align__(16) __half Ah[32][NF];        // agg tile fp16
    __shared__ __align__(16) float  Os[32][OS_LD];     // GEMM result fp32
    int tid = threadIdx.x;
    int row0 = blockIdx.x * 32;
    for (int i = tid; i < NF * NF; i += 256) Wh[i] = __float2half(W1[i]);

    const __half* inh = (const __half*)g_x16;
    int wid = tid >> 5, lane = tid & 31;
    int sub = lane >> 3;
    int fc  = (lane & 7) * 8;
#pragma unroll
    for (int j = 0; j < 4; j++) {
        int nl = (wid << 2) + j;
        int node = row0 + nl;
        float acc[8];
        agg64_node(inh, g_row_ptr[node], g_row_ptr[node + 1], sub, fc, acc);
        if (lane < 8) {
            float ni = g_norm_in[node];
#pragma unroll
            for (int q = 0; q < 8; q++) Ah[nl][fc + q] = __float2half(acc[q] * ni);
        }
    }
    __syncthreads();

    // wmma: 2x4 tiles of 16x16, one per warp, K-loop of 4
    {
        int mt = wid >> 2, nt = wid & 3;
        wmma::fragment<wmma::accumulator, 16, 16, 16, float> fC;
        wmma::fill_fragment(fC, 0.f);
#pragma unroll
        for (int k = 0; k < 4; k++) {
            wmma::fragment<wmma::matrix_a, 16, 16, 16, __half, wmma::row_major> fA;
            wmma::fragment<wmma::matrix_b, 16, 16, 16, __half, wmma::row_major> fB;
            wmma::load_matrix_sync(fA, &Ah[mt * 16][k * 16], NF);
            wmma::load_matrix_sync(fB, &Wh[(k * 16) * NF + nt * 16], NF);
            wmma::mma_sync(fC, fA, fB, fC);
        }
        wmma::store_matrix_sync(&Os[mt * 16][nt * 16], fC, OS_LD, wmma::mem_row_major);
    }
    __syncthreads();

    // epilogue: bias + relu + norm_out -> g_h1 fp16
    int er = tid >> 3;
    int ec = (tid & 7) * 8;
    int g = row0 + er;
    float so = g_norm_out[g];
#pragma unroll
    for (int q = 0; q < 8; q += 2) {
        float o0 = fmaxf(Os[er][ec + q]     + b1[ec + q],     0.f) * so;
        float o1 = fmaxf(Os[er][ec + q + 1] + b1[ec + q + 1], 0.f) * so;
        g_h1[g * 32 + ((ec + q) >> 1)] = __floats2half2_rn(o0, o1);
    }
}

// layer 2 + fused W3: t3 = (relu(aggW2+b2)*norm_out) @ W3  (all wmma) ------
__global__ __launch_bounds__(256) void k_layer2(const float* __restrict__ W2,
                                                const float* __restrict__ b2,
                                                const float* __restrict__ W3) {
    __shared__ __align__(16) __half Wh[NF * NF];       // W2 fp16
    __shared__ __align__(16) __half W3h[NF * NC];      // W3 fp16
    __shared__ __align__(16) __half Ah[32][NF];        // agg tile / h2 tile fp16
    __shared__ __align__(16) float  Os[32][OS_LD];
    int tid = threadIdx.x;
    int row0 = blockIdx.x * 32;
    for (int i = tid; i < NF * NF; i += 256) Wh[i] = __float2half(W2[i]);
    for (int i = tid; i < NF * NC; i += 256) W3h[i] = __float2half(W3[i]);

    const __half* inh = (const __half*)g_h1;
    int wid = tid >> 5, lane = tid & 31;
    int sub = lane >> 3;
    int fc  = (lane & 7) * 8;
#pragma unroll
    for (int j = 0; j < 4; j++) {
        int nl = (wid << 2) + j;
        int node = row0 + nl;
        float acc[8];
        agg64_node(inh, g_row_ptr[node], g_row_ptr[node + 1], sub, fc, acc);
        if (lane < 8) {
            float ni = g_norm_in[node];
#pragma unroll
            for (int q = 0; q < 8; q++) Ah[nl][fc + q] = __float2half(acc[q] * ni);
        }
    }
    __syncthreads();

    // GEMM 1: Os = Ah @ W2
    {
        int mt = wid >> 2, nt = wid & 3;
        wmma::fragment<wmma::accumulator, 16, 16, 16, float> fC;
        wmma::fill_fragment(fC, 0.f);
#pragma unroll
        for (int k = 0; k < 4; k++) {
            wmma::fragment<wmma::matrix_a, 16, 16, 16, __half, wmma::row_major> fA;
            wmma::fragment<wmma::matrix_b, 16, 16, 16, __half, wmma::row_major> fB;
            wmma::load_matrix_sync(fA, &Ah[mt * 16][k * 16], NF);
            wmma::load_matrix_sync(fB, &Wh[(k * 16) * NF + nt * 16], NF);
            wmma::mma_sync(fC, fA, fB, fC);
        }
        wmma::store_matrix_sync(&Os[mt * 16][nt * 16], fC, OS_LD, wmma::mem_row_major);
    }
    __syncthreads();

    // epilogue 1: h2 = relu(Os + b2) * norm_out  -> back into Ah (fp16)
    {
        int er = tid >> 3;
        int ec = (tid & 7) * 8;
        float so = g_norm_out[row0 + er];
#pragma unroll
        for (int q = 0; q < 8; q++)
            Ah[er][ec + q] = __float2half(fmaxf(Os[er][ec + q] + b2[ec + q], 0.f) * so);
    }
    __syncthreads();

    // GEMM 2: Os[:, :32] = Ah @ W3  (warps 0-3)
    if (wid < 4) {
        int mt = wid >> 1, nt = wid & 1;
        wmma::fragment<wmma::accumulator, 16, 16, 16, float> fC;
        wmma::fill_fragment(fC, 0.f);
#pragma unroll
        for (int k = 0; k < 4; k++) {
            wmma::fragment<wmma::matrix_a, 16, 16, 16, __half, wmma::row_major> fA;
            wmma::fragment<wmma::matrix_b, 16, 16, 16, __half, wmma::row_major> fB;
            wmma::load_matrix_sync(fA, &Ah[mt * 16][k * 16], NF);
            wmma::load_matrix_sync(fB, &W3h[(k * 16) * NC + nt * 16], NC);
            wmma::mma_sync(fC, fA, fB, fC);
        }
        wmma::store_matrix_sync(&Os[mt * 16][nt * 16], fC, OS_LD, wmma::mem_row_major);
    }
    __syncthreads();

    // epilogue 2: t3 fp16
    {
        int er = tid >> 3;
        int ec = (tid & 7) * 4;
        int g = row0 + er;
        g_t3[g * 16 + (ec >> 1)]     = __floats2half2_rn(Os[er][ec],     Os[er][ec + 1]);
        g_t3[g * 16 + (ec >> 1) + 1] = __floats2half2_rn(Os[er][ec + 2], Os[er][ec + 3]);
    }
}

// ---------------- final: out = norm_in * Agg(t3) + b3 ---------------------
__global__ void k_out(const float* __restrict__ b3, float* __restrict__ out) {
    int gt = blockIdx.x * blockDim.x + threadIdx.x;
    int w = gt >> 5, lane = gt & 31;
    int sub = lane >> 3;
    int fc  = (lane & 7) * 4;
    const __half* t3 = (const __half*)g_t3;
    int beg = g_row_ptr[w], end = g_row_ptr[w + 1];
    float acc[4] = {};
    int e = beg;
    for (; e + 7 < end; e += 8) {
        int i0 = g_edge_src[e + sub];
        int i1 = g_edge_src[e + 4 + sub];
        uint2 a = *(const uint2*)&t3[i0 * NC + fc];
        uint2 b = *(const uint2*)&t3[i1 * NC + fc];
        float2 f;
        f = __half22float2(*(const __half2*)&a.x); acc[0] += f.x; acc[1] += f.y;
        f = __half22float2(*(const __half2*)&a.y); acc[2] += f.x; acc[3] += f.y;
        f = __half22float2(*(const __half2*)&b.x); acc[0] += f.x; acc[1] += f.y;
        f = __half22float2(*(const __half2*)&b.y); acc[2] += f.x; acc[3] += f.y;
    }
    for (; e < end; e += 4) {
        int eid = e + sub;
        uint2 v = make_uint2(0u, 0u);
        if (eid < end) {
            int s = g_edge_src[eid];
            v = *(const uint2*)&t3[s * NC + fc];
        }
        float2 f;
        f = __half22float2(*(const __half2*)&v.x); acc[0] += f.x; acc[1] += f.y;
        f = __half22float2(*(const __half2*)&v.y); acc[2] += f.x; acc[3] += f.y;
    }
#pragma unroll
    for (int q = 0; q < 4; q++) {
        acc[q] += __shfl_xor_sync(0xffffffffu, acc[q], 8);
        acc[q] += __shfl_xor_sync(0xffffffffu, acc[q], 16);
    }
    if (lane < 8) {
        float ni = g_norm_in[w];
        float4 bb = *(const float4*)&b3[fc];
        float4 o;
        o.x = acc[0] * ni + bb.x;
        o.y = acc[1] * ni + bb.y;
        o.z = acc[2] * ni + bb.z;
        o.w = acc[3] * ni + bb.w;
        *(float4*)&out[w * NC + fc] = o;
    }
}

// ---------------- launch -------------------------------------------------
// Fork/join on a second (non-blocking) stream; streams & events are created
// once (resource setup only — the captured work is identical every call).
extern "C" void kernel_launch(void* const* d_in, const int* in_sizes, int n_in,
                              void* d_out, int out_size) {
    const float* x   = (const float*)d_in[0];
    const int*   src = (const int*)d_in[1];
    const int*   dst = (const int*)d_in[2];
    const float* W1  = (const float*)d_in[3];
    const float* b1  = (const float*)d_in[4];
    const float* W2  = (const float*)d_in[5];
    const float* b2  = (const float*)d_in[6];
    const float* W3  = (const float*)d_in[7];
    const float* b3  = (const float*)d_in[8];
    float* out = (float*)d_out;

    static cudaStream_t s2 = nullptr;
    static cudaEvent_t evA = nullptr, evB = nullptr, evC = nullptr, evD = nullptr;
    if (s2 == nullptr) {
        cudaStreamCreateWithFlags(&s2, cudaStreamNonBlocking);
        cudaEventCreateWithFlags(&evA, cudaEventDisableTiming);
        cudaEventCreateWithFlags(&evB, cudaEventDisableTiming);
        cudaEventCreateWithFlags(&evC, cudaEventDisableTiming);
        cudaEventCreateWithFlags(&evD, cudaEventDisableTiming);
    }

    const int NB_EDGE4 = (NE / 4 + 255) / 256;          // 1563
    const int NB_PRE   = (NN * (NF / 4) + 255) / 256;   // 6250
    const int NB_OUT   = NN * 32 / 256;                 // 12500

    // fork: hist_out on s2 concurrent with hist_in on main stream
    cudaEventRecord(evA, 0);
    cudaStreamWaitEvent(s2, evA, 0);
    k_hist_out<<<NB_EDGE4, 256, 0, s2>>>((const int4*)src);
    k_hist_in<<<NB_EDGE4, 256>>>((const int4*)dst);
    cudaEventRecord(evB, s2);
    cudaStreamWaitEvent(0, evB, 0);

    k_scan1<<<SCAN_NB, SCAN_T>>>();

    // fork: prescale (needs only norm_out) concurrent with scan3 + scatter
    cudaEventRecord(evC, 0);
    cudaStreamWaitEvent(s2, evC, 0);
    k_prescale<<<NB_PRE, 256, 0, s2>>>(x);
    k_scan3<<<SCAN_NB, SCAN_T>>>();
    k_scatter<<<NB_EDGE4, 256>>>((const int4*)src, (const int4*)dst);
    cudaEventRecord(evD, s2);
    cudaStreamWaitEvent(0, evD, 0);

    k_layer1<<<NN / 32, 256>>>(W1, b1);
    k_layer2<<<NN / 32, 256>>>(W2, b2, W3);
    k_out<<<NB_OUT, 256>>>(b3, out);
}